// round 1
// baseline (speedup 1.0000x reference)
#include <cuda_runtime.h>

// Precomputed effective matrix: state = W * r, where r = (c0c1, c0s1, s0c1, s0s1)
// is real and W = L2 * L1 * D (4x4 complex). Stored row-major as float2.
__device__ float2 g_W[16];

__device__ __forceinline__ float2 cmul(float2 a, float2 b) {
    return make_float2(a.x * b.x - a.y * b.y, a.x * b.y + a.y * b.x);
}
__device__ __forceinline__ float2 cadd(float2 a, float2 b) {
    return make_float2(a.x + b.x, a.y + b.y);
}

// One-thread prep: compose the fixed 4x4 complex matrix from q_weights.
__global__ void prep_kernel(const float* __restrict__ qw) {
    if (threadIdx.x != 0 || blockIdx.x != 0) return;

    float2 W[4][4];
    #pragma unroll
    for (int i = 0; i < 4; i++)
        #pragma unroll
        for (int j = 0; j < 4; j++)
            W[i][j] = make_float2(0.f, 0.f);
    // W init = D = diag(1, -i, -i, -1)   (folds the -i factors of RX|0> amps)
    W[0][0] = make_float2(1.f, 0.f);
    W[1][1] = make_float2(0.f, -1.f);
    W[2][2] = make_float2(0.f, -1.f);
    W[3][3] = make_float2(-1.f, 0.f);

    for (int l = 0; l < 2; l++) {
        // Build Rot gates for wires 0,1:  RZ(om) RY(th) RZ(phi)
        float2 g[2][2][2];
        for (int w = 0; w < 2; w++) {
            float phi = qw[l * 6 + w * 3 + 0];
            float th  = qw[l * 6 + w * 3 + 1];
            float om  = qw[l * 6 + w * 3 + 2];
            float ct = cosf(0.5f * th), st = sinf(0.5f * th);
            float a = 0.5f * (phi + om), b = 0.5f * (phi - om);
            float ca = cosf(a), sa = sinf(a), cb = cosf(b), sb = sinf(b);
            g[w][0][0] = make_float2(ct * ca, -ct * sa);   //  e^{-i(phi+om)/2} ct
            g[w][0][1] = make_float2(-st * cb, -st * sb);  // -e^{ i(phi-om)/2} st
            g[w][1][0] = make_float2(st * cb, -st * sb);   //  e^{-i(phi-om)/2} st
            g[w][1][1] = make_float2(ct * ca,  ct * sa);   //  e^{ i(phi+om)/2} ct
        }

        float2 T[4][4], W2[4][4];
        // Gate on qubit 0 (row index i, stride 2):
        // T[(i,j)][m] = sum_{i'} g0[i][i'] * W[(i',j)][m]
        for (int i = 0; i < 2; i++)
            for (int j = 0; j < 2; j++)
                for (int m = 0; m < 4; m++)
                    T[i * 2 + j][m] = cadd(cmul(g[0][i][0], W[0 * 2 + j][m]),
                                           cmul(g[0][i][1], W[1 * 2 + j][m]));
        // Gate on qubit 1 (col index j, stride 1):
        // W2[(i,j)][m] = sum_{j'} g1[j][j'] * T[(i,j')][m]
        for (int i = 0; i < 2; i++)
            for (int j = 0; j < 2; j++)
                for (int m = 0; m < 4; m++)
                    W2[i * 2 + j][m] = cadd(cmul(g[1][j][0], T[i * 2 + 0][m]),
                                            cmul(g[1][j][1], T[i * 2 + 1][m]));
        // CNOT(control=0, target=1): new[(i,j)] = old[(i, j XOR i)]
        for (int i = 0; i < 2; i++)
            for (int j = 0; j < 2; j++)
                for (int m = 0; m < 4; m++)
                    T[i * 2 + j][m] = W2[i * 2 + (j ^ i)][m];
        // CNOT(control=1, target=0): new[(i,j)] = old[(i XOR j, j)]
        for (int i = 0; i < 2; i++)
            for (int j = 0; j < 2; j++)
                for (int m = 0; m < 4; m++)
                    W[i * 2 + j][m] = T[(i ^ j) * 2 + j][m];
    }

    for (int j = 0; j < 4; j++)
        for (int m = 0; m < 4; m++)
            g_W[j * 4 + m] = W[j][m];
}

__device__ __forceinline__ void eval_sample(
    float a0, float a1,
    const float wr[4][4], const float wi[4][4],
    float& z0, float& z1)
{
    const float PI_2 = 1.57079632679489662f;
    float s0, c0, s1, c1;
    __sincosf(a0 * PI_2, &s0, &c0);
    __sincosf(a1 * PI_2, &s1, &c1);
    float r0 = c0 * c1, r1 = c0 * s1, r2 = s0 * c1, r3 = s0 * s1;

    float p[4];
    #pragma unroll
    for (int j = 0; j < 4; j++) {
        float re = wr[j][0] * r0 + wr[j][1] * r1 + wr[j][2] * r2 + wr[j][3] * r3;
        float im = wi[j][0] * r0 + wi[j][1] * r1 + wi[j][2] * r2 + wi[j][3] * r3;
        p[j] = re * re + im * im;
    }
    z0 = (p[0] + p[1]) - (p[2] + p[3]);  // <Z> wire 0: +,+,-,-
    z1 = (p[0] + p[2]) - (p[1] + p[3]);  // <Z> wire 1: +,-,+,-
}

// 2 samples per thread: one float4 in, one float4 out (128-bit transactions).
__global__ void __launch_bounds__(256) qcirc_kernel(
    const float4* __restrict__ noise, float4* __restrict__ out, int n)
{
    int idx = blockIdx.x * blockDim.x + threadIdx.x;
    if (idx >= n) return;

    // Load uniform 4x4 complex matrix (8 x float4, L1/L2-resident after wave 1)
    float wr[4][4], wi[4][4];
    const float4* wp = reinterpret_cast<const float4*>(g_W);
    #pragma unroll
    for (int j = 0; j < 4; j++) {
        float4 a = __ldg(&wp[j * 2 + 0]);   // W[j][0], W[j][1]
        float4 b = __ldg(&wp[j * 2 + 1]);   // W[j][2], W[j][3]
        wr[j][0] = a.x; wi[j][0] = a.y;
        wr[j][1] = a.z; wi[j][1] = a.w;
        wr[j][2] = b.x; wi[j][2] = b.y;
        wr[j][3] = b.z; wi[j][3] = b.w;
    }

    float4 nz = noise[idx];
    float4 res;
    eval_sample(nz.x, nz.y, wr, wi, res.x, res.y);
    eval_sample(nz.z, nz.w, wr, wi, res.z, res.w);
    out[idx] = res;
}

extern "C" void kernel_launch(void* const* d_in, const int* in_sizes, int n_in,
                              void* d_out, int out_size) {
    const float* noise = (const float*)d_in[0];     // [B, 2] f32
    const float* qw    = (const float*)d_in[1];     // [2, 2, 3] f32

    prep_kernel<<<1, 32>>>(qw);

    int n = in_sizes[0] / 4;   // float4 count = B/2 (2 samples per thread)
    int threads = 256;
    int blocks = (n + threads - 1) / threads;
    qcirc_kernel<<<blocks, threads>>>(
        (const float4*)noise, (float4*)d_out, n);
}